// round 5
// baseline (speedup 1.0000x reference)
#include <cuda_runtime.h>
#include <float.h>

// fm [B=4, C=256, H=50, W=50] f32, rois [R=300,5] f32 -> out [R,256,7,7] f32.
#define PH 7
#define PW 7
#define C_ 256
#define H_ 50
#define W_ 50
#define HW (H_ * W_)
#define NCHW 4                        // channels per warp
#define WPB 8                         // warps per block
#define CGRP (C_ / NCHW)              // 64 channel-groups per roi
#define PITCH 66                      // smem column pitch (64 cols + 2 pad)

__device__ __forceinline__ int clampi(int v, int lo, int hi) {
    return min(max(v, lo), hi);
}

// Warp = (roi r, 4-channel group). Lanes along x: dense coalesced row loads,
// warp-private smem column-max buffer, no block-wide syncs.
__global__ __launch_bounds__(WPB * 32) void roi_pool_kernel(
        const float* __restrict__ fm,
        const float* __restrict__ rois,
        float* __restrict__ out) {
    __shared__ float scol[WPB][NCHW][PITCH];

    const int lane = threadIdx.x & 31;
    const int wid  = threadIdx.x >> 5;
    const int gw   = blockIdx.x * WPB + wid;      // 0 .. R*CGRP-1 (exact)
    const int r    = gw >> 6;                     // / CGRP
    const int cg   = gw & (CGRP - 1);

    // ---- ROI box (warp-uniform; jnp.round == rintf under RN) ----
    const float* rp = rois + r * 5;
    const int b  = (int)__ldg(rp + 4);            // float truncation
    int x0 = clampi((int)rintf(__ldg(rp + 0)), 0, W_ - 1);
    int x1 = clampi((int)rintf(__ldg(rp + 2)), 0, W_ - 1);
    int y0 = clampi((int)rintf(__ldg(rp + 1)), 0, H_ - 1);
    int y1 = clampi((int)rintf(__ldg(rp + 3)), 0, H_ - 1);
    x1 = max(x1, x0 + 1);                         // edges may reach 50;
    y1 = max(y1, y0 + 1);                         // reads stay <= 49
    const int w = x1 - x0;                        // 1..49
    const int h = y1 - y0;

    // ---- bin-compute role (lanes 0..27): ch = lane/7, pw = lane%7 ----
    const int ch = lane / PW;
    const int pw = lane - ch * PW;
    const int ws = (pw * w) / PW;                          // relative to x0
    const int bw = ((pw + 1) * w + PW - 1) / PW - ws;      // 1..8
    float* op = out + (((size_t)r * C_ + cg * NCHW + ch) * PH) * PW + pw;

    const float* fb = fm + (size_t)(b * C_ + cg * NCHW) * HW + x0;

    for (int ph = 0; ph < PH; ++ph) {
        const int hs = y0 + (ph * h) / PH;
        const int he = y0 + ((ph + 1) * h + PH - 1) / PH;  // ceil
        const int sh = he - hs;

        // ---- column maxes down the strip, 4 channels, lanes along x ----
        if (lane < w) {
            float c0 = -FLT_MAX, c1 = -FLT_MAX, c2 = -FLT_MAX, c3 = -FLT_MAX;
            const float* p = fb + hs * W_ + lane;
            for (int y = 0; y < sh; ++y, p += W_) {
                c0 = fmaxf(c0, __ldg(p));
                c1 = fmaxf(c1, __ldg(p + 1 * HW));
                c2 = fmaxf(c2, __ldg(p + 2 * HW));
                c3 = fmaxf(c3, __ldg(p + 3 * HW));
            }
            scol[wid][0][lane] = c0;
            scol[wid][1][lane] = c1;
            scol[wid][2][lane] = c2;
            scol[wid][3][lane] = c3;
        }
        if (w > 32) {                                       // warp-uniform
            if (lane + 32 < w) {
                float c0 = -FLT_MAX, c1 = -FLT_MAX, c2 = -FLT_MAX, c3 = -FLT_MAX;
                const float* p = fb + hs * W_ + lane + 32;
                for (int y = 0; y < sh; ++y, p += W_) {
                    c0 = fmaxf(c0, __ldg(p));
                    c1 = fmaxf(c1, __ldg(p + 1 * HW));
                    c2 = fmaxf(c2, __ldg(p + 2 * HW));
                    c3 = fmaxf(c3, __ldg(p + 3 * HW));
                }
                scol[wid][0][lane + 32] = c0;
                scol[wid][1][lane + 32] = c1;
                scol[wid][2][lane + 32] = c2;
                scol[wid][3][lane + 32] = c3;
            }
        }
        __syncwarp();

        // ---- 28 lanes: segmented max over [ws, ws+bw) for (ch, pw) ----
        if (lane < NCHW * PW) {
            const float* s = scol[wid][ch];
            float m = -FLT_MAX;
            for (int i = 0; i < bw; ++i)
                m = fmaxf(m, s[ws + i]);
            op[ph * PW] = m;
        }
        __syncwarp();      // protect scol before next strip overwrites it
    }
}

extern "C" void kernel_launch(void* const* d_in, const int* in_sizes, int n_in,
                              void* d_out, int out_size) {
    const float* fm   = (const float*)d_in[0];
    const float* rois = (const float*)d_in[1];
    float* out = (float*)d_out;

    int R = in_sizes[1] / 5;                       // 300
    int total_warps = R * CGRP;                    // 19200
    int blocks = total_warps / WPB;                // 2400 (exact)
    roi_pool_kernel<<<blocks, WPB * 32>>>(fm, rois, out);
}